// round 1
// baseline (speedup 1.0000x reference)
#include <cuda_runtime.h>

// SharedSharedLoss: mean off-diagonal pairwise squared L2 distance / C.
// Algebraic identity: sum_{i,j} ||a_i - a_j||^2 = 2N * sum_i ||a_i||^2 - 2 * ||sum_i a_i||^2
// => single pass over the 4096x512 input: S2 (sum of squares) + 512 column sums.

#define N_ROWS 4096
#define N_COLS 512
#define N_COLS4 128            // float4 groups per row
#define GRID1 256              // blocks in pass 1
#define BLK1 128               // threads per block (one float4 column-slice each)
#define ROWS_PER_BLK (N_ROWS / GRID1)   // 16

// Deterministic scratch (no float atomics anywhere).
__device__ float g_colpart[GRID1 * N_COLS];   // per-block column-sum partials
__device__ float g_s2part[GRID1];             // per-block sum-of-squares partials

__global__ __launch_bounds__(BLK1) void pass1_kernel(const float* __restrict__ A) {
    const int t = threadIdx.x;            // 0..127: owns cols [4t, 4t+3]
    const int b = blockIdx.x;             // 0..255

    const float4* __restrict__ A4 = reinterpret_cast<const float4*>(A);

    float c0 = 0.f, c1 = 0.f, c2 = 0.f, c3 = 0.f;
    float s2 = 0.f;

    #pragma unroll 4
    for (int r = b; r < N_ROWS; r += GRID1) {
        float4 v = A4[r * N_COLS4 + t];
        c0 += v.x; c1 += v.y; c2 += v.z; c3 += v.w;
        s2 += v.x * v.x + v.y * v.y + v.z * v.z + v.w * v.w;
    }

    // Column-sum partials: coalesced float4 store.
    reinterpret_cast<float4*>(g_colpart)[b * N_COLS4 + t] = make_float4(c0, c1, c2, c3);

    // Block-reduce s2 (4 warps).
    __shared__ float warp_s2[4];
    #pragma unroll
    for (int off = 16; off > 0; off >>= 1)
        s2 += __shfl_down_sync(0xFFFFFFFFu, s2, off);
    if ((t & 31) == 0) warp_s2[t >> 5] = s2;
    __syncthreads();
    if (t == 0) {
        float tot = warp_s2[0] + warp_s2[1] + warp_s2[2] + warp_s2[3];
        g_s2part[b] = tot;
    }
}

__global__ __launch_bounds__(512) void pass2_kernel(float* __restrict__ out) {
    const int c = threadIdx.x;            // 0..511 (one column each)

    // Sum this column's 256 block partials (coalesced across threads).
    float colsum = 0.f;
    #pragma unroll 8
    for (int b = 0; b < GRID1; b++)
        colsum += g_colpart[b * N_COLS + c];

    __shared__ double snrm[512];
    __shared__ double ss2[512];

    snrm[c] = (double)colsum * (double)colsum;
    ss2[c]  = (c < GRID1) ? (double)g_s2part[c] : 0.0;
    __syncthreads();

    // Tree reduce both.
    #pragma unroll
    for (int off = 256; off > 0; off >>= 1) {
        if (c < off) {
            snrm[c] += snrm[c + off];
            ss2[c]  += ss2[c + off];
        }
        __syncthreads();
    }

    if (c == 0) {
        const double N = (double)N_ROWS;
        const double C = (double)N_COLS;
        double S2 = ss2[0];       // sum of squares of all elements
        double NS = snrm[0];      // || column sums ||^2
        double total = (2.0 * N * S2 - 2.0 * NS) / C;   // sum of sims over all (i,j)
        out[0] = (float)(total / (N * (N - 1.0)));
    }
}

extern "C" void kernel_launch(void* const* d_in, const int* in_sizes, int n_in,
                              void* d_out, int out_size) {
    const float* A = (const float*)d_in[0];
    float* out = (float*)d_out;
    (void)in_sizes; (void)n_in; (void)out_size;

    pass1_kernel<<<GRID1, BLK1>>>(A);
    pass2_kernel<<<1, 512>>>(out);
}

// round 2
// speedup vs baseline: 1.8349x; 1.8349x over previous
#include <cuda_runtime.h>

// SharedSharedLoss: mean off-diagonal pairwise squared L2 distance / C.
// Identity: sum_{i,j} ||a_i - a_j||^2 = 2N * S2 - 2 * ||colsum||^2
//   S2 = sum of squares of all elements, colsum = per-column sums.
// One streaming pass over the 4096x512 fp32 input (8 MB), then a tiny reduce.

#define N_ROWS 4096
#define N_COLS 512
#define N_COLS4 128                 // float4 groups per row
#define GRID1 128                   // pass-1 blocks (single wave on 148 SMs)
#define BLK1 256                    // 8 warps: two row-halves x 128 col-groups
#define ROWS_PER_BLK (N_ROWS / GRID1)   // 32
#define ROWS_PER_THREAD (ROWS_PER_BLK / 2)  // 16 (fully unrolled -> MLP 16)

// Deterministic scratch (no float atomics anywhere).
__device__ float g_colpart[GRID1 * N_COLS];   // per-block column-sum partials (256 KB)
__device__ float g_s2part[GRID1];             // per-block sum-of-squares partials

__global__ __launch_bounds__(BLK1) void pass1_kernel(const float* __restrict__ A) {
    const int t = threadIdx.x;
    const int g = t & 127;           // col-group (float4)
    const int h = t >> 7;            // row-half (0 or 1)
    const int b = blockIdx.x;

    const float4* __restrict__ A4 = reinterpret_cast<const float4*>(A);

    float4 c = make_float4(0.f, 0.f, 0.f, 0.f);
    float s2 = 0.f;

    // Rows b*32 + h + 2*i, i = 0..15 — 16 independent loads, fully unrolled.
    const int base = (b * ROWS_PER_BLK + h) * N_COLS4 + g;
    #pragma unroll
    for (int i = 0; i < ROWS_PER_THREAD; i++) {
        float4 v = A4[base + i * 2 * N_COLS4];
        c.x += v.x; c.y += v.y; c.z += v.z; c.w += v.w;
        s2 += v.x * v.x + v.y * v.y + v.z * v.z + v.w * v.w;
    }

    __shared__ float4 sh[BLK1];
    __shared__ float warp_s2[BLK1 / 32];

    sh[t] = c;

    // Warp-reduce s2 (8 warps).
    #pragma unroll
    for (int off = 16; off > 0; off >>= 1)
        s2 += __shfl_down_sync(0xFFFFFFFFu, s2, off);
    if ((t & 31) == 0) warp_s2[t >> 5] = s2;
    __syncthreads();

    // Combine the two row-halves -> one 512-float partial row per block.
    if (t < 128) {
        float4 a = sh[t];
        float4 d = sh[t + 128];
        reinterpret_cast<float4*>(g_colpart)[b * N_COLS4 + t] =
            make_float4(a.x + d.x, a.y + d.y, a.z + d.z, a.w + d.w);
    }
    if (t == 0) {
        float tot = 0.f;
        #pragma unroll
        for (int w = 0; w < BLK1 / 32; w++) tot += warp_s2[w];
        g_s2part[b] = tot;
    }
}

__global__ __launch_bounds__(512) void pass2_kernel(float* __restrict__ out) {
    const int t = threadIdx.x;       // 0..511
    const int g = t & 127;           // col-group
    const int s = t >> 7;            // row-slice (0..3), 32 partial rows each

    const float4* __restrict__ P4 = reinterpret_cast<const float4*>(g_colpart);

    // Each thread sums 32 partial rows for its 4 columns — coalesced float4.
    float4 acc = make_float4(0.f, 0.f, 0.f, 0.f);
    #pragma unroll 8
    for (int i = 0; i < GRID1 / 4; i++) {
        float4 v = P4[(s * (GRID1 / 4) + i) * N_COLS4 + g];
        acc.x += v.x; acc.y += v.y; acc.z += v.z; acc.w += v.w;
    }

    __shared__ float4 sh[512];
    sh[t] = acc;
    __syncthreads();

    // Combine 4 slices, square column sums, reduce; also reduce s2 partials.
    double dnrm = 0.0, ds2 = 0.0;
    if (t < 128) {
        float4 a = sh[t], b = sh[t + 128], c = sh[t + 256], d = sh[t + 384];
        double x = (double)(a.x + b.x + c.x + d.x);
        double y = (double)(a.y + b.y + c.y + d.y);
        double z = (double)(a.z + b.z + c.z + d.z);
        double w = (double)(a.w + b.w + c.w + d.w);
        dnrm = x * x + y * y + z * z + w * w;
        ds2  = (double)g_s2part[t];
    }

    // Reduce 128 doubles (4 active warps) via shuffles + shared.
    __shared__ double w_nrm[4];
    __shared__ double w_s2[4];
    if (t < 128) {
        #pragma unroll
        for (int off = 16; off > 0; off >>= 1) {
            dnrm += __shfl_down_sync(0xFFFFFFFFu, dnrm, off);
            ds2  += __shfl_down_sync(0xFFFFFFFFu, ds2, off);
        }
        if ((t & 31) == 0) { w_nrm[t >> 5] = dnrm; w_s2[t >> 5] = ds2; }
    }
    __syncthreads();

    if (t == 0) {
        double S2 = w_s2[0] + w_s2[1] + w_s2[2] + w_s2[3];
        double NS = w_nrm[0] + w_nrm[1] + w_nrm[2] + w_nrm[3];
        const double N = (double)N_ROWS;
        const double C = (double)N_COLS;
        double total = (2.0 * N * S2 - 2.0 * NS) / C;
        out[0] = (float)(total / (N * (N - 1.0)));
    }
}

extern "C" void kernel_launch(void* const* d_in, const int* in_sizes, int n_in,
                              void* d_out, int out_size) {
    const float* A = (const float*)d_in[0];
    float* out = (float*)d_out;
    (void)in_sizes; (void)n_in; (void)out_size;

    pass1_kernel<<<GRID1, BLK1>>>(A);
    pass2_kernel<<<1, 512>>>(out);
}

// round 3
// speedup vs baseline: 2.3008x; 1.2539x over previous
#include <cuda_runtime.h>

// SharedSharedLoss: mean off-diagonal pairwise squared L2 distance / C.
// Identity: sum_{i,j} ||a_i - a_j||^2 = 2N * S2 - 2 * ||colsum||^2
// Single fused kernel: 16 column-strips x 8 row-chunks = 128 blocks.
// Each block reduces its strip to 32 column partials + 1 s2 partial (16 KB total),
// and the last block to finish does the tiny final reduce (threadfence pattern).

#define N_ROWS 4096
#define N_COLS 512
#define N_COLS4 128                  // float4 groups per row
#define N_STRIPS 16                  // column strips of 32 cols (8 float4 groups)
#define N_CHUNKS 8                   // row chunks of 512 rows
#define GRID (N_STRIPS * N_CHUNKS)   // 128 blocks
#define BLK 256                      // 8 groups x 32 row-lanes
#define ROWS_PER_CHUNK (N_ROWS / N_CHUNKS)        // 512
#define ROWS_PER_THREAD (ROWS_PER_CHUNK / 32)     // 16 (fully unrolled MLP)

// Deterministic scratch (no float atomics anywhere).
__device__ float g_colpart[GRID * 32];   // [rc*16+cs][32 cols] = 16 KB
__device__ float g_s2part[GRID];
__device__ unsigned int g_count = 0;     // completion counter (reset by last block)

__global__ __launch_bounds__(BLK) void fused_kernel(const float* __restrict__ A,
                                                    float* __restrict__ out) {
    const int t  = threadIdx.x;
    const int g  = t & 7;            // float4 group within strip (0..7)
    const int r0 = t >> 3;           // row lane (0..31)
    const int b  = blockIdx.x;
    const int cs = b & (N_STRIPS - 1);   // column strip
    const int rc = b >> 4;               // row chunk

    const float4* __restrict__ A4 = reinterpret_cast<const float4*>(A);

    // ---- Streaming phase: 512 rows x 32 cols per block ----
    float4 c = make_float4(0.f, 0.f, 0.f, 0.f);
    float s2 = 0.f;

    const int base = (rc * ROWS_PER_CHUNK + r0) * N_COLS4 + cs * 8 + g;
    #pragma unroll
    for (int i = 0; i < ROWS_PER_THREAD; i++) {
        float4 v = A4[base + i * 32 * N_COLS4];
        c.x += v.x; c.y += v.y; c.z += v.z; c.w += v.w;
        s2 += v.x * v.x + v.y * v.y + v.z * v.z + v.w * v.w;
    }

    // ---- Block reduce: colsums over the 32 row-lanes ----
    __shared__ float4 sh[BLK];
    __shared__ float warp_s2[BLK / 32];
    sh[t] = c;

    #pragma unroll
    for (int off = 16; off > 0; off >>= 1)
        s2 += __shfl_down_sync(0xFFFFFFFFu, s2, off);
    if ((t & 31) == 0) warp_s2[t >> 5] = s2;
    __syncthreads();

    // Tree-reduce sh over the r0 dimension (index = g + 8*r0).
    #pragma unroll
    for (int off = 128; off >= 8; off >>= 1) {
        if (t < off) {
            float4 o = sh[t + off];
            float4 m = sh[t];
            sh[t] = make_float4(m.x + o.x, m.y + o.y, m.z + o.z, m.w + o.w);
        }
        __syncthreads();
    }

    if (t < 8)
        reinterpret_cast<float4*>(g_colpart)[b * 8 + t] = sh[t];
    if (t == 0) {
        float tot = 0.f;
        #pragma unroll
        for (int w = 0; w < BLK / 32; w++) tot += warp_s2[w];
        g_s2part[b] = tot;
    }

    // ---- Last-block-done final reduce ----
    __threadfence();
    __syncthreads();
    __shared__ bool isLast;
    if (t == 0) {
        unsigned int old = atomicAdd(&g_count, 1u);
        isLast = (old == GRID - 1);
    }
    __syncthreads();
    if (!isLast) return;

    // Column sums: thread t handles cols t and t+256.
    // g_colpart layout: [(rc*16+cs)*32 + localcol]; col = cs*32+lc -> float index
    // rc*512 + col. Coalesced across threads.
    double dnrm = 0.0;
    #pragma unroll
    for (int k = 0; k < 2; k++) {
        const int col = t + k * 256;
        float s = 0.f;
        #pragma unroll
        for (int r = 0; r < N_CHUNKS; r++)
            s += g_colpart[r * N_COLS + col];
        dnrm += (double)s * (double)s;
    }
    double ds2 = (t < GRID) ? (double)g_s2part[t] : 0.0;

    // Reduce 256 doubles (8 warps) via shuffles + shared.
    __shared__ double w_nrm[BLK / 32];
    __shared__ double w_s2d[BLK / 32];
    #pragma unroll
    for (int off = 16; off > 0; off >>= 1) {
        dnrm += __shfl_down_sync(0xFFFFFFFFu, dnrm, off);
        ds2  += __shfl_down_sync(0xFFFFFFFFu, ds2, off);
    }
    if ((t & 31) == 0) { w_nrm[t >> 5] = dnrm; w_s2d[t >> 5] = ds2; }
    __syncthreads();

    if (t == 0) {
        double NS = 0.0, S2 = 0.0;
        #pragma unroll
        for (int w = 0; w < BLK / 32; w++) { NS += w_nrm[w]; S2 += w_s2d[w]; }
        const double N = (double)N_ROWS;
        const double C = (double)N_COLS;
        double total = (2.0 * N * S2 - 2.0 * NS) / C;
        out[0] = (float)(total / (N * (N - 1.0)));
        g_count = 0;   // reset for next graph replay
    }
}

extern "C" void kernel_launch(void* const* d_in, const int* in_sizes, int n_in,
                              void* d_out, int out_size) {
    const float* A = (const float*)d_in[0];
    float* out = (float*)d_out;
    (void)in_sizes; (void)n_in; (void)out_size;

    fused_kernel<<<GRID, BLK>>>(A, out);
}